// round 1
// baseline (speedup 1.0000x reference)
#include <cuda_runtime.h>

#define IH 256
#define IW 256
#define HWX 65536

// ---------------- scratch (static device allocations; no cudaMalloc) ----------------
__device__ float g_bufA[64 * HWX];
__device__ float g_bufB[64 * HWX];
__device__ float g_raw[216 * HWX];
__device__ float g_col[576 * HWX];
__device__ float g_cat[128 * HWX];

// ---------------- tiled 3x3 conv, pad=1, stride=1, NCHW / OIHW ----------------
// block: 256 threads (16x16 logical), tile 64 wide x 16 high pixels, 8 out-channels/block.
// grid: (W/64, H/16, Cout/8)
template <int CIN, bool LRELU>
__global__ __launch_bounds__(256) void conv3x3_k(
    const float* __restrict__ x, const float* __restrict__ wgt,
    const float* __restrict__ bias, float* __restrict__ y)
{
    __shared__ float s_w[CIN * 72];     // [cin][oc(8)][tap(9)]
    __shared__ float s_t[18][68];       // input tile (18 x 66 used, padded row)

    const int tid = threadIdx.x;
    const int tx = tid & 15;            // 16 threads across, 4 px each -> 64 cols
    const int ty = tid >> 4;            // 16 rows
    const int h0 = blockIdx.y * 16;
    const int w0 = blockIdx.x * 64;
    const int ocb = blockIdx.z * 8;

    // stage all weights for this oc-block
    for (int idx = tid; idx < CIN * 72; idx += 256) {
        int cin = idx / 72;
        int r = idx - cin * 72;
        int oc = r / 9;
        int tap = r - oc * 9;
        s_w[idx] = wgt[((ocb + oc) * CIN + cin) * 9 + tap];
    }

    float acc[8][4];
#pragma unroll
    for (int oc = 0; oc < 8; ++oc) {
#pragma unroll
        for (int p = 0; p < 4; ++p) acc[oc][p] = 0.f;
    }

#pragma unroll 1
    for (int cin = 0; cin < CIN; ++cin) {
        const float* xp = x + cin * HWX;
        for (int idx = tid; idx < 18 * 66; idx += 256) {
            int r = idx / 66;
            int c = idx - r * 66;
            int gy = h0 - 1 + r;
            int gx = w0 - 1 + c;
            float v = 0.f;
            if (gy >= 0 && gy < IH && gx >= 0 && gx < IW) v = xp[gy * IW + gx];
            s_t[r][c] = v;
        }
        __syncthreads();

        float v[3][6];
#pragma unroll
        for (int r = 0; r < 3; ++r)
#pragma unroll
            for (int c = 0; c < 6; ++c)
                v[r][c] = s_t[ty + r][tx * 4 + c];

        const float* wrow = &s_w[cin * 72];
#pragma unroll
        for (int oc = 0; oc < 8; ++oc) {
#pragma unroll
            for (int kyy = 0; kyy < 3; ++kyy) {
#pragma unroll
                for (int kxx = 0; kxx < 3; ++kxx) {
                    float wv = wrow[oc * 9 + kyy * 3 + kxx];
#pragma unroll
                    for (int p = 0; p < 4; ++p)
                        acc[oc][p] = fmaf(v[kyy][kxx + p], wv, acc[oc][p]);
                }
            }
        }
        __syncthreads();
    }

    const int h = h0 + ty;
    const int wc = w0 + tx * 4;
#pragma unroll
    for (int oc = 0; oc < 8; ++oc) {
        float bv = bias[ocb + oc];
        float4 o;
        float* op = reinterpret_cast<float*>(&o);
#pragma unroll
        for (int p = 0; p < 4; ++p) {
            float r = acc[oc][p] + bv;
            if (LRELU) r = (r >= 0.f) ? r : 0.1f * r;
            op[p] = r;
        }
        *reinterpret_cast<float4*>(&y[(ocb + oc) * HWX + h * IW + wc]) = o;
    }
}

// ---------------- deformable sampling -> col[ (g*8+c)*9+k ][ p ] ----------------
// block (32, 8): 32 consecutive pixels x 8 groups. grid: 65536/32 = 2048
__global__ __launch_bounds__(256) void sample_k(
    const float* __restrict__ feat, const float* __restrict__ raw,
    const float* __restrict__ flow, float* __restrict__ col)
{
    const int txl = threadIdx.x;
    const int g = threadIdx.y;
    const int p = blockIdx.x * 32 + txl;
    const int h = p >> 8;
    const int w = p & 255;

    const float fy = flow[HWX + p];  // reversed: y-offset channel gets flow[1]
    const float fx = flow[p];        // x-offset channel gets flow[0]

#pragma unroll 1
    for (int k = 0; k < 9; ++k) {
        const int kyv = k / 3 - 1;
        const int kxv = k % 3 - 1;
        const int ch = g * 18 + k * 2;

        float ry = raw[ch * HWX + p];
        float rx = raw[(ch + 1) * HWX + p];
        float rm = raw[(144 + g * 9 + k) * HWX + p];

        // saturating-safe tanh: 1 - 2/(e^{2v}+1)
        float ey = __expf(2.f * ry);
        float oy = 10.f * (1.f - 2.f / (ey + 1.f));
        float ex = __expf(2.f * rx);
        float ox = 10.f * (1.f - 2.f / (ex + 1.f));
        float m = 1.f / (1.f + __expf(-rm));

        float py = (float)h + (float)kyv + oy + fy;
        float px = (float)w + (float)kxv + ox + fx;
        float y0f = floorf(py), x0f = floorf(px);
        float ly = py - y0f, lx = px - x0f;
        int y0 = (int)y0f, x0 = (int)x0f;
        int y1 = y0 + 1, x1 = x0 + 1;

        bool vy0 = (y0 >= 0) && (y0 < IH);
        bool vy1 = (y1 >= 0) && (y1 < IH);
        bool vx0 = (x0 >= 0) && (x0 < IW);
        bool vx1 = (x1 >= 0) && (x1 < IW);

        float w00 = (vy0 && vx0) ? (1.f - ly) * (1.f - lx) * m : 0.f;
        float w01 = (vy0 && vx1) ? (1.f - ly) * lx * m : 0.f;
        float w10 = (vy1 && vx0) ? ly * (1.f - lx) * m : 0.f;
        float w11 = (vy1 && vx1) ? ly * lx * m : 0.f;

        int y0c = min(max(y0, 0), IH - 1), y1c = min(max(y1, 0), IH - 1);
        int x0c = min(max(x0, 0), IW - 1), x1c = min(max(x1, 0), IW - 1);
        int i00 = y0c * IW + x0c, i01 = y0c * IW + x1c;
        int i10 = y1c * IW + x0c, i11 = y1c * IW + x1c;

        const float* xb = feat + (size_t)g * 8 * HWX;
#pragma unroll
        for (int c = 0; c < 8; ++c) {
            const float* xc = xb + c * HWX;
            float s = w00 * xc[i00] + w01 * xc[i01] + w10 * xc[i10] + w11 * xc[i11];
            col[((size_t)((g * 8 + c) * 9 + k)) * HWX + p] = s;
        }
    }
}

// ---------------- GEMM: out[64][65536] = W[64][576] @ col[576][65536] + b ----------------
// block: 256 threads, tile 1024 pixels x 16 oc. grid: (64, 4)
__global__ __launch_bounds__(256) void gemm_col_k(
    const float* __restrict__ col, const float* __restrict__ wgt,
    const float* __restrict__ bias, float* __restrict__ out)
{
    __shared__ float s_w[576 * 16];   // [i][oc]
    __shared__ float s_c[2][1024];

    const int tid = threadIdx.x;
    const int pb = blockIdx.x * 1024;
    const int ocb = blockIdx.y * 16;

    for (int idx = tid; idx < 576 * 16; idx += 256) {
        int i = idx >> 4;
        int oc = idx & 15;
        s_w[idx] = wgt[(ocb + oc) * 576 + i];
    }

    float acc[16][4];
#pragma unroll
    for (int oc = 0; oc < 16; ++oc) {
#pragma unroll
        for (int p = 0; p < 4; ++p) acc[oc][p] = 0.f;
    }

#pragma unroll 1
    for (int i0 = 0; i0 < 576; i0 += 2) {
        for (int idx = tid; idx < 2048; idx += 256) {
            int ii = idx >> 10;
            int pp = idx & 1023;
            s_c[ii][pp] = col[(size_t)(i0 + ii) * HWX + pb + pp];
        }
        __syncthreads();
#pragma unroll
        for (int ii = 0; ii < 2; ++ii) {
            float4 cv = reinterpret_cast<float4*>(s_c[ii])[tid];
            const float* wr = &s_w[(i0 + ii) * 16];
#pragma unroll
            for (int oc = 0; oc < 16; ++oc) {
                float wv = wr[oc];
                acc[oc][0] = fmaf(cv.x, wv, acc[oc][0]);
                acc[oc][1] = fmaf(cv.y, wv, acc[oc][1]);
                acc[oc][2] = fmaf(cv.z, wv, acc[oc][2]);
                acc[oc][3] = fmaf(cv.w, wv, acc[oc][3]);
            }
        }
        __syncthreads();
    }

#pragma unroll
    for (int oc = 0; oc < 16; ++oc) {
        float bv = bias[ocb + oc];
        float4 o;
        o.x = acc[oc][0] + bv;
        o.y = acc[oc][1] + bv;
        o.z = acc[oc][2] + bv;
        o.w = acc[oc][3] + bv;
        *reinterpret_cast<float4*>(&out[(size_t)(ocb + oc) * HWX + pb + tid * 4]) = o;
    }
}

// ---------------- host side ----------------
extern "C" void kernel_launch(void* const* d_in, const int* in_sizes, int n_in,
                              void* d_out, int out_size)
{
    (void)in_sizes; (void)n_in; (void)out_size;

    float *bufA, *bufB, *raw, *colp, *cat;
    cudaGetSymbolAddress((void**)&bufA, g_bufA);
    cudaGetSymbolAddress((void**)&bufB, g_bufB);
    cudaGetSymbolAddress((void**)&raw, g_raw);
    cudaGetSymbolAddress((void**)&colp, g_col);
    cudaGetSymbolAddress((void**)&cat, g_cat);

    const float* feat[2]  = {(const float*)d_in[0], (const float*)d_in[1]};
    const float* extra[2] = {(const float*)d_in[2], (const float*)d_in[3]};
    const float* flow[2]  = {(const float*)d_in[4], (const float*)d_in[5]};

    dim3 cgrid64(4, 16, 8);    // Cout=64
    dim3 cgrid216(4, 16, 27);  // Cout=216
    dim3 sblk(32, 8);

    for (int br = 0; br < 2; ++br) {
        int wb = 6 + br * 8;  // off{1,2}_w0 base
        const float* w0 = (const float*)d_in[wb + 0];
        const float* b0 = (const float*)d_in[wb + 1];
        const float* w1 = (const float*)d_in[wb + 2];
        const float* b1 = (const float*)d_in[wb + 3];
        const float* w2 = (const float*)d_in[wb + 4];
        const float* b2 = (const float*)d_in[wb + 5];
        const float* w3 = (const float*)d_in[wb + 6];
        const float* b3 = (const float*)d_in[wb + 7];
        const float* dw = (const float*)d_in[22 + br * 2];
        const float* db = (const float*)d_in[23 + br * 2];

        conv3x3_k<128, true><<<cgrid64, 256>>>(extra[br], w0, b0, bufA);
        conv3x3_k<64, true><<<cgrid64, 256>>>(bufA, w1, b1, bufB);
        conv3x3_k<64, true><<<cgrid64, 256>>>(bufB, w2, b2, bufA);
        conv3x3_k<64, false><<<cgrid216, 256>>>(bufA, w3, b3, raw);

        sample_k<<<2048, sblk>>>(feat[br], raw, flow[br], colp);
        gemm_col_k<<<dim3(64, 4), 256>>>(colp, dw, db, cat + (size_t)br * 64 * HWX);
    }

    const float* fw = (const float*)d_in[26];
    const float* fb = (const float*)d_in[27];
    conv3x3_k<128, false><<<cgrid64, 256>>>(cat, fw, fb, (float*)d_out);
}

// round 2
// speedup vs baseline: 1.7303x; 1.7303x over previous
#include <cuda_runtime.h>

#define IH 256
#define IW 256
#define HWX 65536

// ---------------- scratch (static device allocations; no cudaMalloc) ----------------
__device__ float g_bufA[2 * 64 * HWX];
__device__ float g_bufB[2 * 64 * HWX];
__device__ float g_raw[2 * 216 * HWX];
__device__ float g_col[2 * 576 * HWX];
__device__ float g_cat[128 * HWX];

// ---------------- tiled 3x3 conv, pad=1, stride=1, NCHW / OIHW ----------------
// block: 256 threads. tile 64 wide x 32 high, 8 px/thread (4 across x 2 rows),
// 8 out-channels per block. Dual-branch batched via blockIdx.z.
// grid: (4, 8, nBranches * COUT/8)
template <int CIN, int COUT, bool LRELU>
__global__ __launch_bounds__(256, 2) void conv3x3_k(
    const float* __restrict__ x0p, const float* __restrict__ x1p,
    const float* __restrict__ w0p, const float* __restrict__ w1p,
    const float* __restrict__ b0p, const float* __restrict__ b1p,
    float* __restrict__ y0p, float* __restrict__ y1p)
{
    constexpr int ZPB = COUT / 8;
    __shared__ float s_w[CIN * 72];                  // [cin][oc(8)][tap(9)]
    __shared__ __align__(16) float s_t[2][34][68];   // two cin tiles per barrier round

    const int tid = threadIdx.x;
    const int tx = tid & 15;
    const int ty = tid >> 4;
    const int h0 = blockIdx.y * 32;
    const int w0 = blockIdx.x * 64;

    int zb = blockIdx.z;
    const float* x; const float* wgt; const float* bias; float* y;
    if (zb < ZPB) { x = x0p; wgt = w0p; bias = b0p; y = y0p; }
    else { zb -= ZPB; x = x1p; wgt = w1p; bias = b1p; y = y1p; }
    const int ocb = zb * 8;

    for (int idx = tid; idx < CIN * 72; idx += 256) {
        int cin = idx / 72;
        int r = idx - cin * 72;
        int oc = r / 9;
        int tap = r - oc * 9;
        s_w[idx] = wgt[((ocb + oc) * CIN + cin) * 9 + tap];
    }

    const bool interior = (h0 >= 1) && (h0 <= IH - 33) && (w0 >= 1) && (w0 <= IW - 65);

    float acc[8][8];
#pragma unroll
    for (int oc = 0; oc < 8; ++oc)
#pragma unroll
        for (int p = 0; p < 8; ++p) acc[oc][p] = 0.f;

#pragma unroll 1
    for (int c0 = 0; c0 < CIN; c0 += 2) {
#pragma unroll
        for (int t = 0; t < 2; ++t) {
            const float* xp = x + (size_t)(c0 + t) * HWX;
            if (interior) {
                const float* base = xp + (h0 - 1) * IW + (w0 - 1);
#pragma unroll
                for (int i = 0; i < 9; ++i) {
                    int idx = tid + i * 256;
                    if (idx < 34 * 66) {
                        int r = idx / 66;
                        int c = idx - r * 66;
                        s_t[t][r][c] = base[r * IW + c];
                    }
                }
            } else {
#pragma unroll
                for (int i = 0; i < 9; ++i) {
                    int idx = tid + i * 256;
                    if (idx < 34 * 66) {
                        int r = idx / 66;
                        int c = idx - r * 66;
                        int gy = h0 - 1 + r, gx = w0 - 1 + c;
                        float v = 0.f;
                        if (gy >= 0 && gy < IH && gx >= 0 && gx < IW) v = xp[gy * IW + gx];
                        s_t[t][r][c] = v;
                    }
                }
            }
        }
        __syncthreads();

#pragma unroll
        for (int t = 0; t < 2; ++t) {
            float v[4][8];
#pragma unroll
            for (int r = 0; r < 4; ++r) {
                float4 a = *reinterpret_cast<const float4*>(&s_t[t][2 * ty + r][tx * 4]);
                float4 b = *reinterpret_cast<const float4*>(&s_t[t][2 * ty + r][tx * 4 + 4]);
                v[r][0] = a.x; v[r][1] = a.y; v[r][2] = a.z; v[r][3] = a.w;
                v[r][4] = b.x; v[r][5] = b.y; v[r][6] = b.z; v[r][7] = b.w;
            }
            const float* wrow = &s_w[(c0 + t) * 72];
#pragma unroll
            for (int oc = 0; oc < 8; ++oc) {
#pragma unroll
                for (int kyy = 0; kyy < 3; ++kyy) {
#pragma unroll
                    for (int kxx = 0; kxx < 3; ++kxx) {
                        float wv = wrow[oc * 9 + kyy * 3 + kxx];
#pragma unroll
                        for (int p = 0; p < 4; ++p) {
                            acc[oc][p]     = fmaf(v[kyy][kxx + p],     wv, acc[oc][p]);
                            acc[oc][4 + p] = fmaf(v[kyy + 1][kxx + p], wv, acc[oc][4 + p]);
                        }
                    }
                }
            }
        }
        __syncthreads();
    }

    const int h = h0 + 2 * ty;
    const int wc = w0 + tx * 4;
#pragma unroll
    for (int oc = 0; oc < 8; ++oc) {
        float bv = bias[ocb + oc];
#pragma unroll
        for (int r = 0; r < 2; ++r) {
            float4 o;
            float* op = reinterpret_cast<float*>(&o);
#pragma unroll
            for (int p = 0; p < 4; ++p) {
                float val = acc[oc][r * 4 + p] + bv;
                if (LRELU) val = (val >= 0.f) ? val : 0.1f * val;
                op[p] = val;
            }
            *reinterpret_cast<float4*>(&y[(size_t)(ocb + oc) * HWX + (h + r) * IW + wc]) = o;
        }
    }
}

// ---------------- deformable sampling -> col[ (g*8+c)*9+k ][ p ] ----------------
// block (32, 8): 32 consecutive pixels x 8 groups. grid: (2048, 2 branches)
__global__ __launch_bounds__(256) void sample_k(
    const float* __restrict__ f0, const float* __restrict__ f1,
    const float* __restrict__ rawb,
    const float* __restrict__ fl0, const float* __restrict__ fl1,
    float* __restrict__ colb)
{
    const int br = blockIdx.y;
    const float* feat = br ? f1 : f0;
    const float* raw = rawb + (size_t)br * 216 * HWX;
    const float* flow = br ? fl1 : fl0;
    float* col = colb + (size_t)br * 576 * HWX;

    const int txl = threadIdx.x;
    const int g = threadIdx.y;
    const int p = blockIdx.x * 32 + txl;
    const int h = p >> 8;
    const int w = p & 255;

    const float fy = flow[HWX + p];  // reversed: y-offset channel gets flow[1]
    const float fx = flow[p];        // x-offset channel gets flow[0]

#pragma unroll 1
    for (int k = 0; k < 9; ++k) {
        const int kyv = k / 3 - 1;
        const int kxv = k % 3 - 1;
        const int ch = g * 18 + k * 2;

        float ry = raw[(size_t)ch * HWX + p];
        float rx = raw[(size_t)(ch + 1) * HWX + p];
        float rm = raw[(size_t)(144 + g * 9 + k) * HWX + p];

        float ey = __expf(2.f * ry);
        float oy = 10.f * (1.f - 2.f / (ey + 1.f));
        float ex = __expf(2.f * rx);
        float ox = 10.f * (1.f - 2.f / (ex + 1.f));
        float m = 1.f / (1.f + __expf(-rm));

        float py = (float)h + (float)kyv + oy + fy;
        float px = (float)w + (float)kxv + ox + fx;
        float y0f = floorf(py), x0f = floorf(px);
        float ly = py - y0f, lx = px - x0f;
        int y0 = (int)y0f, x0 = (int)x0f;
        int y1 = y0 + 1, x1 = x0 + 1;

        bool vy0 = (y0 >= 0) && (y0 < IH);
        bool vy1 = (y1 >= 0) && (y1 < IH);
        bool vx0 = (x0 >= 0) && (x0 < IW);
        bool vx1 = (x1 >= 0) && (x1 < IW);

        float w00 = (vy0 && vx0) ? (1.f - ly) * (1.f - lx) * m : 0.f;
        float w01 = (vy0 && vx1) ? (1.f - ly) * lx * m : 0.f;
        float w10 = (vy1 && vx0) ? ly * (1.f - lx) * m : 0.f;
        float w11 = (vy1 && vx1) ? ly * lx * m : 0.f;

        int y0c = min(max(y0, 0), IH - 1), y1c = min(max(y1, 0), IH - 1);
        int x0c = min(max(x0, 0), IW - 1), x1c = min(max(x1, 0), IW - 1);
        int i00 = y0c * IW + x0c, i01 = y0c * IW + x1c;
        int i10 = y1c * IW + x0c, i11 = y1c * IW + x1c;

        const float* xb = feat + (size_t)g * 8 * HWX;
#pragma unroll
        for (int c = 0; c < 8; ++c) {
            const float* xc = xb + (size_t)c * HWX;
            float s = w00 * xc[i00] + w01 * xc[i01] + w10 * xc[i10] + w11 * xc[i11];
            col[((size_t)((g * 8 + c) * 9 + k)) * HWX + p] = s;
        }
    }
}

// ---------------- GEMM: out[64][65536] = W[64][576] @ col[576][65536] + b ----------------
// block: 256 threads, tile 2048 pixels x 8 oc, 8 px x 8 oc per thread.
// grid: (32, 8, 2 branches)
__global__ __launch_bounds__(256, 2) void gemm_col_k(
    const float* __restrict__ colb,
    const float* __restrict__ wg0, const float* __restrict__ wg1,
    const float* __restrict__ bi0, const float* __restrict__ bi1,
    float* __restrict__ outb)
{
    __shared__ float s_w[576 * 8];                  // [i][oc]
    __shared__ __align__(16) float s_c[4][2048];

    const int tid = threadIdx.x;
    const int pb = blockIdx.x * 2048;
    const int ocb = blockIdx.y * 8;
    const int br = blockIdx.z;
    const float* col = colb + (size_t)br * 576 * HWX;
    const float* wgt = br ? wg1 : wg0;
    const float* bias = br ? bi1 : bi0;
    float* out = outb + (size_t)br * 64 * HWX;

    for (int idx = tid; idx < 576 * 8; idx += 256) {
        int i = idx >> 3;
        int oc = idx & 7;
        s_w[idx] = wgt[(ocb + oc) * 576 + i];
    }

    float acc[8][8];
#pragma unroll
    for (int oc = 0; oc < 8; ++oc)
#pragma unroll
        for (int p = 0; p < 8; ++p) acc[oc][p] = 0.f;

#pragma unroll 1
    for (int i0 = 0; i0 < 576; i0 += 4) {
#pragma unroll
        for (int i = 0; i < 8; ++i) {
            int flat = tid + i * 256;   // float4 units, 0..2047
            int row = flat >> 9;
            int c4 = flat & 511;
            *reinterpret_cast<float4*>(&s_c[row][c4 * 4]) =
                *reinterpret_cast<const float4*>(&col[(size_t)(i0 + row) * HWX + pb + c4 * 4]);
        }
        __syncthreads();
#pragma unroll
        for (int kk = 0; kk < 4; ++kk) {
            float4 a = *reinterpret_cast<const float4*>(&s_c[kk][tid * 4]);
            float4 b = *reinterpret_cast<const float4*>(&s_c[kk][1024 + tid * 4]);
            const float* wr = &s_w[(i0 + kk) * 8];
#pragma unroll
            for (int oc = 0; oc < 8; ++oc) {
                float wv = wr[oc];
                acc[oc][0] = fmaf(a.x, wv, acc[oc][0]);
                acc[oc][1] = fmaf(a.y, wv, acc[oc][1]);
                acc[oc][2] = fmaf(a.z, wv, acc[oc][2]);
                acc[oc][3] = fmaf(a.w, wv, acc[oc][3]);
                acc[oc][4] = fmaf(b.x, wv, acc[oc][4]);
                acc[oc][5] = fmaf(b.y, wv, acc[oc][5]);
                acc[oc][6] = fmaf(b.z, wv, acc[oc][6]);
                acc[oc][7] = fmaf(b.w, wv, acc[oc][7]);
            }
        }
        __syncthreads();
    }

#pragma unroll
    for (int oc = 0; oc < 8; ++oc) {
        float bv = bias[ocb + oc];
        float4 o1, o2;
        o1.x = acc[oc][0] + bv; o1.y = acc[oc][1] + bv;
        o1.z = acc[oc][2] + bv; o1.w = acc[oc][3] + bv;
        o2.x = acc[oc][4] + bv; o2.y = acc[oc][5] + bv;
        o2.z = acc[oc][6] + bv; o2.w = acc[oc][7] + bv;
        *reinterpret_cast<float4*>(&out[(size_t)(ocb + oc) * HWX + pb + tid * 4]) = o1;
        *reinterpret_cast<float4*>(&out[(size_t)(ocb + oc) * HWX + pb + 1024 + tid * 4]) = o2;
    }
}

// ---------------- host side ----------------
extern "C" void kernel_launch(void* const* d_in, const int* in_sizes, int n_in,
                              void* d_out, int out_size)
{
    (void)in_sizes; (void)n_in; (void)out_size;

    float *bufA, *bufB, *raw, *colp, *cat;
    cudaGetSymbolAddress((void**)&bufA, g_bufA);
    cudaGetSymbolAddress((void**)&bufB, g_bufB);
    cudaGetSymbolAddress((void**)&raw, g_raw);
    cudaGetSymbolAddress((void**)&colp, g_col);
    cudaGetSymbolAddress((void**)&cat, g_cat);

    const float* feat0  = (const float*)d_in[0];
    const float* feat1  = (const float*)d_in[1];
    const float* extra0 = (const float*)d_in[2];
    const float* extra1 = (const float*)d_in[3];
    const float* flow0  = (const float*)d_in[4];
    const float* flow1  = (const float*)d_in[5];

    const size_t OFF64 = (size_t)64 * HWX;

    // offset-branch weights: off1 at 6..13, off2 at 14..21
    const float* W[2][4]; const float* Bb[2][4];
    for (int br = 0; br < 2; ++br)
        for (int j = 0; j < 4; ++j) {
            W[br][j]  = (const float*)d_in[6 + br * 8 + j * 2];
            Bb[br][j] = (const float*)d_in[6 + br * 8 + j * 2 + 1];
        }
    const float* dw1 = (const float*)d_in[22];
    const float* db1 = (const float*)d_in[23];
    const float* dw2 = (const float*)d_in[24];
    const float* db2 = (const float*)d_in[25];
    const float* fw  = (const float*)d_in[26];
    const float* fb  = (const float*)d_in[27];

    dim3 g64(4, 8, 16);    // dual-branch, Cout=64
    dim3 g216(4, 8, 54);   // dual-branch, Cout=216
    dim3 gfus(4, 8, 8);    // single, Cout=64

    conv3x3_k<128, 64, true><<<g64, 256>>>(extra0, extra1, W[0][0], W[1][0], Bb[0][0], Bb[1][0],
                                           bufA, bufA + OFF64);
    conv3x3_k<64, 64, true><<<g64, 256>>>(bufA, bufA + OFF64, W[0][1], W[1][1], Bb[0][1], Bb[1][1],
                                          bufB, bufB + OFF64);
    conv3x3_k<64, 64, true><<<g64, 256>>>(bufB, bufB + OFF64, W[0][2], W[1][2], Bb[0][2], Bb[1][2],
                                          bufA, bufA + OFF64);
    conv3x3_k<64, 216, false><<<g216, 256>>>(bufA, bufA + OFF64, W[0][3], W[1][3], Bb[0][3], Bb[1][3],
                                             raw, raw + (size_t)216 * HWX);

    sample_k<<<dim3(2048, 2), dim3(32, 8)>>>(feat0, feat1, raw, flow0, flow1, colp);
    gemm_col_k<<<dim3(32, 8, 2), 256>>>(colp, dw1, dw2, db1, db2, cat);

    conv3x3_k<128, 64, false><<<gfus, 256>>>(cat, cat, fw, fw, fb, fb, (float*)d_out, (float*)d_out);
}

// round 5
// speedup vs baseline: 2.0756x; 1.1996x over previous
#include <cuda_runtime.h>
#include <cstdint>

#define IH 256
#define IW 256
#define HWX 65536

// ---------------- scratch (static device allocations; no cudaMalloc) ----------------
__device__ float g_bufA[2 * 64 * HWX];
__device__ float g_bufB[2 * 64 * HWX];
__device__ float g_raw[2 * 216 * HWX];
__device__ float g_col[2 * 576 * HWX];
__device__ float g_cat[128 * HWX];

__device__ __forceinline__ uint32_t smem_u32(const void* p) {
    return (uint32_t)__cvta_generic_to_shared(p);
}
__device__ __forceinline__ void cp16(uint32_t daddr, const void* src, int src_sz) {
    asm volatile("cp.async.cg.shared.global [%0], [%1], 16, %2;"
                 :: "r"(daddr), "l"(src), "r"(src_sz));
}
__device__ __forceinline__ void cp_commit() {
    asm volatile("cp.async.commit_group;");
}
__device__ __forceinline__ void cp_wait1() {
    asm volatile("cp.async.wait_group 1;");
}
__device__ __forceinline__ void cp_wait0() {
    asm volatile("cp.async.wait_group 0;");
}

// ---------------- tiled 3x3 conv, pad=1, stride=1, NCHW / OIHW ----------------
// block: 256 threads. tile 64 wide x 32 high, 8 px/thread (4 across x 2 rows),
// 8 out-channels per block. Dual-branch batched via blockIdx.z.
// Tile staged 72 wide (pixels w0-4 .. w0+67) via cp.async 16B chunks, zero-filled halos.
// Double-buffered over cin pairs. Weights in smem as [cin][tap][oc] for float4 reads.
// grid: (4, 8, nBranches * COUT/8)
#define TROW 72
#define TSZ  (34 * TROW)   // floats per cin tile

template <int CIN, int COUT, bool LRELU>
__global__ __launch_bounds__(256, 2) void conv3x3_k(
    const float* __restrict__ x0p, const float* __restrict__ x1p,
    const float* __restrict__ w0p, const float* __restrict__ w1p,
    const float* __restrict__ b0p, const float* __restrict__ b1p,
    float* __restrict__ y0p, float* __restrict__ y1p)
{
    constexpr int ZPB = COUT / 8;
    extern __shared__ float smem[];
    float* s_w = smem;                 // CIN*72
    float* s_t = smem + CIN * 72;      // 4 cin tiles (2 pairs) of TSZ

    const int tid = threadIdx.x;
    const int tx = tid & 15;
    const int ty = tid >> 4;
    const int h0 = blockIdx.y * 32;
    const int w0 = blockIdx.x * 64;

    int zb = blockIdx.z;
    const float* x; const float* wgt; const float* bias; float* y;
    if (zb < ZPB) { x = x0p; wgt = w0p; bias = b0p; y = y0p; }
    else { zb -= ZPB; x = x1p; wgt = w1p; bias = b1p; y = y1p; }
    const int ocb = zb * 8;

    // weights -> smem, layout [cin][tap(9)][oc(8)]
    for (int idx = tid; idx < CIN * 72; idx += 256) {
        int cin = idx / 72;
        int r = idx - cin * 72;
        int tap = r >> 3;
        int oc = r & 7;
        s_w[idx] = wgt[((ocb + oc) * CIN + cin) * 9 + tap];
    }

    const uint32_t st_base = smem_u32(s_t);

    // stage one cin tile into buffer slot `slot` (0..3) via cp.async
    auto stage_cin = [&](int cin, int slot) {
        const float* xp = x + (size_t)cin * HWX;
        uint32_t dbase = st_base + (uint32_t)slot * (TSZ * 4);
#pragma unroll
        for (int i = 0; i < 3; ++i) {
            int idx = tid + i * 256;
            if (idx < 34 * 18) {
                int row = idx / 18;
                int c4 = idx - row * 18;
                int gy = h0 - 1 + row;
                int gx = w0 - 4 + c4 * 4;
                bool valid = (gy >= 0) && (gy < IH) && (gx >= 0) && (gx < IW);
                const float* src = valid ? (xp + gy * IW + gx) : xp;
                cp16(dbase + (uint32_t)(row * TROW + c4 * 4) * 4, src, valid ? 16 : 0);
            }
        }
    };

    float acc[8][8];
#pragma unroll
    for (int oc = 0; oc < 8; ++oc)
#pragma unroll
        for (int p = 0; p < 8; ++p) acc[oc][p] = 0.f;

    // prologue: stage pair 0 into slots 0,1
    stage_cin(0, 0);
    stage_cin(1, 1);
    cp_commit();

    constexpr int NPAIR = CIN / 2;
#pragma unroll 1
    for (int p = 0; p < NPAIR; ++p) {
        if (p + 1 < NPAIR) {
            int s = ((p + 1) & 1) * 2;
            stage_cin(2 * (p + 1), s);
            stage_cin(2 * (p + 1) + 1, s + 1);
            cp_commit();
            cp_wait1();
        } else {
            cp_wait0();
        }
        __syncthreads();

#pragma unroll
        for (int t = 0; t < 2; ++t) {
            const float* sb = s_t + ((p & 1) * 2 + t) * TSZ;
            const float4* w4 = reinterpret_cast<const float4*>(s_w + (2 * p + t) * 72);

            float r0[12], r1[12], r2[12];
            // load rows 2ty, 2ty+1, 2ty+2 (3 x float4 each)
            {
                const float4* rp0 = reinterpret_cast<const float4*>(sb + (2 * ty + 0) * TROW + tx * 4);
                const float4* rp1 = reinterpret_cast<const float4*>(sb + (2 * ty + 1) * TROW + tx * 4);
                const float4* rp2 = reinterpret_cast<const float4*>(sb + (2 * ty + 2) * TROW + tx * 4);
#pragma unroll
                for (int j = 0; j < 3; ++j) {
                    float4 a0 = rp0[j], a1 = rp1[j], a2 = rp2[j];
                    r0[4 * j] = a0.x; r0[4 * j + 1] = a0.y; r0[4 * j + 2] = a0.z; r0[4 * j + 3] = a0.w;
                    r1[4 * j] = a1.x; r1[4 * j + 1] = a1.y; r1[4 * j + 2] = a1.z; r1[4 * j + 3] = a1.w;
                    r2[4 * j] = a2.x; r2[4 * j + 1] = a2.y; r2[4 * j + 2] = a2.z; r2[4 * j + 3] = a2.w;
                }
            }

            // out-row 0: input rows r0,r1,r2
#pragma unroll
            for (int tap = 0; tap < 9; ++tap) {
                const int kyy = tap / 3, kxx = tap - 3 * kyy;
                float4 wa = w4[2 * tap], wb = w4[2 * tap + 1];
                const float* vr = (kyy == 0) ? r0 : ((kyy == 1) ? r1 : r2);
#pragma unroll
                for (int q = 0; q < 4; ++q) {
                    float xv = vr[3 + kxx + q];
                    acc[0][q] = fmaf(xv, wa.x, acc[0][q]);
                    acc[1][q] = fmaf(xv, wa.y, acc[1][q]);
                    acc[2][q] = fmaf(xv, wa.z, acc[2][q]);
                    acc[3][q] = fmaf(xv, wa.w, acc[3][q]);
                    acc[4][q] = fmaf(xv, wb.x, acc[4][q]);
                    acc[5][q] = fmaf(xv, wb.y, acc[5][q]);
                    acc[6][q] = fmaf(xv, wb.z, acc[6][q]);
                    acc[7][q] = fmaf(xv, wb.w, acc[7][q]);
                }
            }

            // reload r0 <- row 2ty+3
            {
                const float4* rp3 = reinterpret_cast<const float4*>(sb + (2 * ty + 3) * TROW + tx * 4);
#pragma unroll
                for (int j = 0; j < 3; ++j) {
                    float4 a = rp3[j];
                    r0[4 * j] = a.x; r0[4 * j + 1] = a.y; r0[4 * j + 2] = a.z; r0[4 * j + 3] = a.w;
                }
            }

            // out-row 1: input rows r1,r2,r0(=row+3)
#pragma unroll
            for (int tap = 0; tap < 9; ++tap) {
                const int kyy = tap / 3, kxx = tap - 3 * kyy;
                float4 wa = w4[2 * tap], wb = w4[2 * tap + 1];
                const float* vr = (kyy == 0) ? r1 : ((kyy == 1) ? r2 : r0);
#pragma unroll
                for (int q = 0; q < 4; ++q) {
                    float xv = vr[3 + kxx + q];
                    acc[0][4 + q] = fmaf(xv, wa.x, acc[0][4 + q]);
                    acc[1][4 + q] = fmaf(xv, wa.y, acc[1][4 + q]);
                    acc[2][4 + q] = fmaf(xv, wa.z, acc[2][4 + q]);
                    acc[3][4 + q] = fmaf(xv, wa.w, acc[3][4 + q]);
                    acc[4][4 + q] = fmaf(xv, wb.x, acc[4][4 + q]);
                    acc[5][4 + q] = fmaf(xv, wb.y, acc[5][4 + q]);
                    acc[6][4 + q] = fmaf(xv, wb.z, acc[6][4 + q]);
                    acc[7][4 + q] = fmaf(xv, wb.w, acc[7][4 + q]);
                }
            }
        }
        __syncthreads();
    }

    const int h = h0 + 2 * ty;
    const int wc = w0 + tx * 4;
#pragma unroll
    for (int oc = 0; oc < 8; ++oc) {
        float bv = bias[ocb + oc];
#pragma unroll
        for (int r = 0; r < 2; ++r) {
            float4 o;
            float* op = reinterpret_cast<float*>(&o);
#pragma unroll
            for (int q = 0; q < 4; ++q) {
                float val = acc[oc][r * 4 + q] + bv;
                if (LRELU) val = (val >= 0.f) ? val : 0.1f * val;
                op[q] = val;
            }
            *reinterpret_cast<float4*>(&y[(size_t)(ocb + oc) * HWX + (h + r) * IW + wc]) = o;
        }
    }
}

// ---------------- deformable sampling -> col[ (g*8+c)*9+k ][ p ] ----------------
// block (32, 8): 32 consecutive pixels x 8 groups. grid: (2048, 2 branches)
__global__ __launch_bounds__(256) void sample_k(
    const float* __restrict__ f0, const float* __restrict__ f1,
    const float* __restrict__ rawb,
    const float* __restrict__ fl0, const float* __restrict__ fl1,
    float* __restrict__ colb)
{
    const int br = blockIdx.y;
    const float* feat = br ? f1 : f0;
    const float* raw = rawb + (size_t)br * 216 * HWX;
    const float* flow = br ? fl1 : fl0;
    float* col = colb + (size_t)br * 576 * HWX;

    const int txl = threadIdx.x;
    const int g = threadIdx.y;
    const int p = blockIdx.x * 32 + txl;
    const int h = p >> 8;
    const int w = p & 255;

    const float fy = flow[HWX + p];  // reversed: y-offset channel gets flow[1]
    const float fx = flow[p];        // x-offset channel gets flow[0]

#pragma unroll 1
    for (int k = 0; k < 9; ++k) {
        const int kyv = k / 3 - 1;
        const int kxv = k % 3 - 1;
        const int ch = g * 18 + k * 2;

        float ry = raw[(size_t)ch * HWX + p];
        float rx = raw[(size_t)(ch + 1) * HWX + p];
        float rm = raw[(size_t)(144 + g * 9 + k) * HWX + p];

        float ey = __expf(2.f * ry);
        float oy = 10.f * (1.f - 2.f / (ey + 1.f));
        float ex = __expf(2.f * rx);
        float ox = 10.f * (1.f - 2.f / (ex + 1.f));
        float m = 1.f / (1.f + __expf(-rm));

        float py = (float)h + (float)kyv + oy + fy;
        float px = (float)w + (float)kxv + ox + fx;
        float y0f = floorf(py), x0f = floorf(px);
        float ly = py - y0f, lx = px - x0f;
        int y0 = (int)y0f, x0 = (int)x0f;
        int y1 = y0 + 1, x1 = x0 + 1;

        bool vy0 = (y0 >= 0) && (y0 < IH);
        bool vy1 = (y1 >= 0) && (y1 < IH);
        bool vx0 = (x0 >= 0) && (x0 < IW);
        bool vx1 = (x1 >= 0) && (x1 < IW);

        float w00 = (vy0 && vx0) ? (1.f - ly) * (1.f - lx) * m : 0.f;
        float w01 = (vy0 && vx1) ? (1.f - ly) * lx * m : 0.f;
        float w10 = (vy1 && vx0) ? ly * (1.f - lx) * m : 0.f;
        float w11 = (vy1 && vx1) ? ly * lx * m : 0.f;

        int y0c = min(max(y0, 0), IH - 1), y1c = min(max(y1, 0), IH - 1);
        int x0c = min(max(x0, 0), IW - 1), x1c = min(max(x1, 0), IW - 1);
        int i00 = y0c * IW + x0c, i01 = y0c * IW + x1c;
        int i10 = y1c * IW + x0c, i11 = y1c * IW + x1c;

        const float* xb = feat + (size_t)g * 8 * HWX;
#pragma unroll
        for (int c = 0; c < 8; ++c) {
            const float* xc = xb + (size_t)c * HWX;
            float s = w00 * __ldg(xc + i00) + w01 * __ldg(xc + i01)
                    + w10 * __ldg(xc + i10) + w11 * __ldg(xc + i11);
            col[((size_t)((g * 8 + c) * 9 + k)) * HWX + p] = s;
        }
    }
}

// ---------------- GEMM: out[64][65536] = W[64][576] @ col[576][65536] + b ----------------
// block: 256 threads, tile 2048 pixels x 8 oc, 8 px x 8 oc per thread.
// cp.async double-buffered k-chunks of 4. grid: (32, 8, 2 branches)
__global__ __launch_bounds__(256, 2) void gemm_col_k(
    const float* __restrict__ colb,
    const float* __restrict__ wg0, const float* __restrict__ wg1,
    const float* __restrict__ bi0, const float* __restrict__ bi1,
    float* __restrict__ outb)
{
    extern __shared__ float smem[];
    float* s_w = smem;                 // 576*8
    float* s_c = smem + 576 * 8;       // 2 buffers x 4 x 2048

    const int tid = threadIdx.x;
    const int pb = blockIdx.x * 2048;
    const int ocb = blockIdx.y * 8;
    const int br = blockIdx.z;
    const float* col = colb + (size_t)br * 576 * HWX;
    const float* wgt = br ? wg1 : wg0;
    const float* bias = br ? bi1 : bi0;
    float* out = outb + (size_t)br * 64 * HWX;

    for (int idx = tid; idx < 576 * 8; idx += 256) {
        int i = idx >> 3;
        int oc = idx & 7;
        s_w[idx] = wgt[(ocb + oc) * 576 + i];
    }

    const uint32_t sc_base = smem_u32(s_c);

    auto stage_chunk = [&](int chunk, int buf) {
        int i0 = chunk * 4;
        uint32_t dbase = sc_base + (uint32_t)buf * (4 * 2048 * 4);
#pragma unroll
        for (int j = 0; j < 8; ++j) {
            int flat = tid + j * 256;          // 16B units, 0..2047
            int row = flat >> 9;
            int c4 = flat & 511;
            cp16(dbase + (uint32_t)(row * 2048 + c4 * 4) * 4,
                 col + (size_t)(i0 + row) * HWX + pb + c4 * 4, 16);
        }
    };

    float acc[8][8];
#pragma unroll
    for (int oc = 0; oc < 8; ++oc)
#pragma unroll
        for (int q = 0; q < 8; ++q) acc[oc][q] = 0.f;

    stage_chunk(0, 0);
    cp_commit();

#pragma unroll 1
    for (int c = 0; c < 144; ++c) {
        if (c + 1 < 144) {
            stage_chunk(c + 1, (c + 1) & 1);
            cp_commit();
            cp_wait1();
        } else {
            cp_wait0();
        }
        __syncthreads();

        const float* sb = s_c + (c & 1) * (4 * 2048);
#pragma unroll
        for (int kk = 0; kk < 4; ++kk) {
            float4 a = *reinterpret_cast<const float4*>(sb + kk * 2048 + tid * 4);
            float4 b = *reinterpret_cast<const float4*>(sb + kk * 2048 + 1024 + tid * 4);
            const float* wr = &s_w[(c * 4 + kk) * 8];
#pragma unroll
            for (int oc = 0; oc < 8; ++oc) {
                float wv = wr[oc];
                acc[oc][0] = fmaf(a.x, wv, acc[oc][0]);
                acc[oc][1] = fmaf(a.y, wv, acc[oc][1]);
                acc[oc][2] = fmaf(a.z, wv, acc[oc][2]);
                acc[oc][3] = fmaf(a.w, wv, acc[oc][3]);
                acc[oc][4] = fmaf(b.x, wv, acc[oc][4]);
                acc[oc][5] = fmaf(b.y, wv, acc[oc][5]);
                acc[oc][6] = fmaf(b.z, wv, acc[oc][6]);
                acc[oc][7] = fmaf(b.w, wv, acc[oc][7]);
            }
        }
        __syncthreads();
    }

#pragma unroll
    for (int oc = 0; oc < 8; ++oc) {
        float bv = bias[ocb + oc];
        float4 o1, o2;
        o1.x = acc[oc][0] + bv; o1.y = acc[oc][1] + bv;
        o1.z = acc[oc][2] + bv; o1.w = acc[oc][3] + bv;
        o2.x = acc[oc][4] + bv; o2.y = acc[oc][5] + bv;
        o2.z = acc[oc][6] + bv; o2.w = acc[oc][7] + bv;
        *reinterpret_cast<float4*>(&out[(size_t)(ocb + oc) * HWX + pb + tid * 4]) = o1;
        *reinterpret_cast<float4*>(&out[(size_t)(ocb + oc) * HWX + pb + 1024 + tid * 4]) = o2;
    }
}

// ---------------- host side ----------------
extern "C" void kernel_launch(void* const* d_in, const int* in_sizes, int n_in,
                              void* d_out, int out_size)
{
    (void)in_sizes; (void)n_in; (void)out_size;

    float *bufA, *bufB, *raw, *colp, *cat;
    cudaGetSymbolAddress((void**)&bufA, g_bufA);
    cudaGetSymbolAddress((void**)&bufB, g_bufB);
    cudaGetSymbolAddress((void**)&raw, g_raw);
    cudaGetSymbolAddress((void**)&colp, g_col);
    cudaGetSymbolAddress((void**)&cat, g_cat);

    const float* feat0  = (const float*)d_in[0];
    const float* feat1  = (const float*)d_in[1];
    const float* extra0 = (const float*)d_in[2];
    const float* extra1 = (const float*)d_in[3];
    const float* flow0  = (const float*)d_in[4];
    const float* flow1  = (const float*)d_in[5];

    const size_t OFF64 = (size_t)64 * HWX;

    const float* W[2][4]; const float* Bb[2][4];
    for (int br = 0; br < 2; ++br)
        for (int j = 0; j < 4; ++j) {
            W[br][j]  = (const float*)d_in[6 + br * 8 + j * 2];
            Bb[br][j] = (const float*)d_in[6 + br * 8 + j * 2 + 1];
        }
    const float* dw1 = (const float*)d_in[22];
    const float* db1 = (const float*)d_in[23];
    const float* dw2 = (const float*)d_in[24];
    const float* db2 = (const float*)d_in[25];
    const float* fw  = (const float*)d_in[26];
    const float* fb  = (const float*)d_in[27];

    const int SM_C128 = (128 * 72 + 4 * TSZ) * 4;   // 76032
    const int SM_C64  = (64 * 72 + 4 * TSZ) * 4;    // 57600
    const int SM_GEMM = (576 * 8 + 2 * 4 * 2048) * 4; // 83968

    cudaFuncSetAttribute(conv3x3_k<128, 64, true>,  cudaFuncAttributeMaxDynamicSharedMemorySize, SM_C128);
    cudaFuncSetAttribute(conv3x3_k<64, 64, true>,   cudaFuncAttributeMaxDynamicSharedMemorySize, SM_C64);
    cudaFuncSetAttribute(conv3x3_k<64, 216, false>, cudaFuncAttributeMaxDynamicSharedMemorySize, SM_C64);
    cudaFuncSetAttribute(conv3x3_k<128, 64, false>, cudaFuncAttributeMaxDynamicSharedMemorySize, SM_C128);
    cudaFuncSetAttribute(gemm_col_k,                cudaFuncAttributeMaxDynamicSharedMemorySize, SM_GEMM);

    dim3 g64(4, 8, 16);    // dual-branch, Cout=64
    dim3 g216(4, 8, 54);   // dual-branch, Cout=216
    dim3 gfus(4, 8, 8);    // single, Cout=64

    conv3x3_k<128, 64, true><<<g64, 256, SM_C128>>>(extra0, extra1, W[0][0], W[1][0], Bb[0][0], Bb[1][0],
                                                    bufA, bufA + OFF64);
    conv3x3_k<64, 64, true><<<g64, 256, SM_C64>>>(bufA, bufA + OFF64, W[0][1], W[1][1], Bb[0][1], Bb[1][1],
                                                  bufB, bufB + OFF64);
    conv3x3_k<64, 64, true><<<g64, 256, SM_C64>>>(bufB, bufB + OFF64, W[0][2], W[1][2], Bb[0][2], Bb[1][2],
                                                  bufA, bufA + OFF64);
    conv3x3_k<64, 216, false><<<g216, 256, SM_C64>>>(bufA, bufA + OFF64, W[0][3], W[1][3], Bb[0][3], Bb[1][3],
                                                     raw, raw + (size_t)216 * HWX);

    sample_k<<<dim3(2048, 2), dim3(32, 8)>>>(feat0, feat1, raw, flow0, flow1, colp);
    gemm_col_k<<<dim3(32, 8, 2), 256, SM_GEMM>>>(colp, dw1, dw2, db1, db2, cat);

    conv3x3_k<128, 64, false><<<gfus, 256, SM_C128>>>(cat, cat, fw, fw, fb, fb, (float*)d_out, (float*)d_out);
}